// round 16
// baseline (speedup 1.0000x reference)
#include <cuda_runtime.h>
#include <cstdint>
#include <math.h>

// IMDCT round 16: R15 + pair-interleaved PQ (b64 stage-2 loads) + pre-packed weights.
//
//   z_col[t] = sum_u W2[t][u]*PQ[u][tau], tau=t&31
//   PQ[f0][tau]    = sum_f1 S[16f1+f0]*cos(pi*f1*(2tau+1)/32)
//   PQ[16+f0][tau] = sum_f1 S[16f1+f0]*sin(pi*f1*(2tau+1)/32)
//   butterfly: row tau+16 = (-1)^f1 * row tau -> E/O partial sums, P = E+-O.
// W2 from input kernels. Epilogue: windowed overlap-add.
//
// Block 128 thr = 4 warps, NSEG=14, NCOLS=16 = 2 groups of 8 cols; 4 blocks/SM.
// PQ: buffer per col-PAIR, word = u*66 + tau*2 + (col&1).
//   stage-1 b32 stores: banks (2f0+2tau+cp) -> conflict-free;
//   stage-2 one b64/u/colpair, lo/hi = col even/odd = FMA2 lanes directly.
// Weights: g_wpA/g_wpB [u][tid64] ulonglong2 of {w,w} pairs (16B lane stride, coalesced).

#define NFREQ    256
#define TFRAMES  4096
#define NSEG     14
#define NCOLS    16
#define TSTR     260                       // smT/Dt col stride (words)
#define SMTW     (NCOLS * TSTR)            // 4160 words
#define PQU      66                        // PQ u-stride (words)
#define PQBUFW   (32 * PQU)                // 2112 words per col-pair buffer
#define SMWORDS  (SMTW + 4 * PQBUFW)       // 12608
#define SMBYTES  (SMWORDS * 4)             // 50,432 B
#define LOUT     1048832

#define FMA2(acc, a, v) \
    asm("fma.rn.f32x2 %0, %1, %2, %0;" : "+l"(acc) : "l"(a), "l"(v))

// cos(k*pi/32), k = 0..63 — folded to FFMA immediates (indices compile-time).
static __device__ constexpr float CP64[64] = {
     1.00000000f,  0.99518473f,  0.98078528f,  0.95694034f,
     0.92387953f,  0.88192126f,  0.83146961f,  0.77301045f,
     0.70710678f,  0.63439328f,  0.55557023f,  0.47139674f,
     0.38268343f,  0.29028468f,  0.19509032f,  0.09801714f,
     0.00000000f, -0.09801714f, -0.19509032f, -0.29028468f,
    -0.38268343f, -0.47139674f, -0.55557023f, -0.63439328f,
    -0.70710678f, -0.77301045f, -0.83146961f, -0.88192126f,
    -0.92387953f, -0.95694034f, -0.98078528f, -0.99518473f,
    -1.00000000f, -0.99518473f, -0.98078528f, -0.95694034f,
    -0.92387953f, -0.88192126f, -0.83146961f, -0.77301045f,
    -0.70710678f, -0.63439328f, -0.55557023f, -0.47139674f,
    -0.38268343f, -0.29028468f, -0.19509032f, -0.09801714f,
     0.00000000f,  0.09801714f,  0.19509032f,  0.29028468f,
     0.38268343f,  0.47139674f,  0.55557023f,  0.63439328f,
     0.70710678f,  0.77301045f,  0.83146961f,  0.88192126f,
     0.92387953f,  0.95694034f,  0.98078528f,  0.99518473f
};

// Pre-packed stage-2 weights: {W2,W2} duplicated pairs.
//   g_wpA[u*64+j] = { dup(W2[j][u]),     dup(W2[j+64][u]) }     (m = 0,1)
//   g_wpB[u*64+j] = { dup(W2[j+128][u]), dup(W2[j+192][u]) }    (m = 2,3)
__device__ ulonglong2 g_wpA[32 * 64];
__device__ ulonglong2 g_wpB[32 * 64];
__device__ float      g_win[512];

static __device__ __forceinline__ unsigned long long dup2(float x) {
    unsigned long long r;
    asm("mov.b64 %0, {%1, %1};" : "=l"(r) : "r"(__float_as_uint(x)));
    return r;
}

__global__ void prep_kernel(const float* __restrict__ kernels)
{
    int idx = blockIdx.x * blockDim.x + threadIdx.x;   // 2560 threads
    if (idx < 2048) {
        int u = idx >> 6, j = idx & 63;
        float r[4];
        #pragma unroll
        for (int m = 0; m < 4; m++) {
            int t = j + 64 * m;
            float wn = sinf((float)M_PI * (float)(2 * (128 + t) + 1) * (1.0f / 1024.0f));
            float sc = 1.0f / (128.0f * wn);
            if (u < 16)
                r[m] = kernels[(128 + t) * 256 + u] * sc;
            else {
                float sgn = (t & 1) ? 1.0f : -1.0f;    // -(-1)^t
                r[m] = sgn * kernels[(128 + t) * 256 + (255 - (u - 16))] * sc;
            }
        }
        ulonglong2 a, bb;
        a.x  = dup2(r[0]); a.y  = dup2(r[1]);
        bb.x = dup2(r[2]); bb.y = dup2(r[3]);
        g_wpA[u * 64 + j] = a;
        g_wpB[u * 64 + j] = bb;
    } else if (idx < 2560) {
        int t = idx - 2048;
        g_win[t] = sinf((float)M_PI * (float)(2 * t + 1) * (1.0f / 1024.0f));
    }
}

__global__ __launch_bounds__(128, 4)
void imdct_main_kernel(const float* __restrict__ spec, float* __restrict__ out)
{
    extern __shared__ float sm[];                      // smT[16][260] ++ PQ[4][2112]
    const int tid  = threadIdx.x;                      // 0..127
    const int lane = tid & 31;
    const int w    = tid >> 5;                         // warp 0..3
    const int cp   = lane >> 4;                        // stage-1 col parity in pair
    const int f0   = lane & 15;                        // stage-1 u-base
    const int b    = blockIdx.y;
    const int s0   = blockIdx.x * NSEG;

    // ---- Stage spec transposed: smT[c][f] = spec[b][f][s0-1+c] ----
    const float* specB = spec + (size_t)b * NFREQ * TFRAMES;
    #pragma unroll 4
    for (int i = tid; i < NFREQ * NCOLS; i += 128) {
        int f = i >> 4, c = i & 15;
        int cg = s0 - 1 + c;
        float v = (cg >= 0 && cg < TFRAMES) ? __ldg(&specB[(size_t)f * TFRAMES + cg]) : 0.0f;
        sm[c * TSTR + f] = v;
    }

    const uint32_t smb = (uint32_t)__cvta_generic_to_shared(sm);
    const uint32_t pqb = smb + SMTW * 4;
    __syncthreads();

    #pragma unroll 1
    for (int G = 0; G < 2; G++) {
        // ======== stage 1: warp w -> col pair (2w, 2w+1); lane (cp,f0) -> col 8G+2w+cp ========
        const float* colp = sm + (8 * G + 2 * w + cp) * TSTR;

        float S[16];
        #pragma unroll
        for (int f1 = 0; f1 < 16; f1++) S[f1] = colp[16 * f1 + f0];

        // buffer w; word = u*66 + tau*2 + cp  (banks 2f0+2tau+cp: conflict-free)
        const uint32_t pqP = pqb + (uint32_t)((w * PQBUFW + f0 * PQU) * 4) + (uint32_t)(cp * 4);
        const uint32_t pqQ = pqP + (uint32_t)(16 * PQU * 4);

        #pragma unroll
        for (int tp = 0; tp < 8; tp++) {               // taus 2tp, 2tp+1 (+16 via butterfly)
            float ep0 = 0.f, op0 = 0.f, eq0 = 0.f, oq0 = 0.f;
            float ep1 = 0.f, op1 = 0.f, eq1 = 0.f, oq1 = 0.f;
            #pragma unroll
            for (int f1 = 0; f1 < 16; f1++) {
                const int k0 = (f1 * (4 * tp + 1)) & 63;
                const int k1 = (f1 * (4 * tp + 3)) & 63;
                const float c0 = CP64[k0], s0c = CP64[(k0 + 48) & 63];
                const float c1 = CP64[k1], s1c = CP64[(k1 + 48) & 63];
                if (f1 & 1) {
                    op0 = fmaf(S[f1], c0, op0);  oq0 = fmaf(S[f1], s0c, oq0);
                    op1 = fmaf(S[f1], c1, op1);  oq1 = fmaf(S[f1], s1c, oq1);
                } else {
                    ep0 = fmaf(S[f1], c0, ep0);  eq0 = fmaf(S[f1], s0c, eq0);
                    ep1 = fmaf(S[f1], c1, ep1);  eq1 = fmaf(S[f1], s1c, eq1);
                }
            }
            const uint32_t o0 = (uint32_t)((2 * tp) * 8);        // tau*2 words -> tau*8 bytes
            const uint32_t o1 = o0 + 8;
            const uint32_t o2 = o0 + 128;                        // tau + 16
            const uint32_t o3 = o2 + 8;
            asm volatile("st.shared.b32 [%0], %1;" :: "r"(pqP + o0), "r"(__float_as_uint(ep0 + op0)));
            asm volatile("st.shared.b32 [%0], %1;" :: "r"(pqP + o1), "r"(__float_as_uint(ep1 + op1)));
            asm volatile("st.shared.b32 [%0], %1;" :: "r"(pqP + o2), "r"(__float_as_uint(ep0 - op0)));
            asm volatile("st.shared.b32 [%0], %1;" :: "r"(pqP + o3), "r"(__float_as_uint(ep1 - op1)));
            asm volatile("st.shared.b32 [%0], %1;" :: "r"(pqQ + o0), "r"(__float_as_uint(eq0 + oq0)));
            asm volatile("st.shared.b32 [%0], %1;" :: "r"(pqQ + o1), "r"(__float_as_uint(eq1 + oq1)));
            asm volatile("st.shared.b32 [%0], %1;" :: "r"(pqQ + o2), "r"(__float_as_uint(eq0 - oq0)));
            asm volatile("st.shared.b32 [%0], %1;" :: "r"(pqQ + o3), "r"(__float_as_uint(eq1 - oq1)));
        }
        __syncthreads();

        // ======== stage 2: half-block per 4 cols (buffers 2h, 2h+1); t = tid64 + 64m ========
        const int tid64 = tid & 63;
        const int h     = tid >> 6;                    // 0 or 1
        unsigned long long z2[4][2];
        #pragma unroll
        for (int m = 0; m < 4; m++) { z2[m][0] = 0; z2[m][1] = 0; }
        const uint32_t pq0 = pqb + (uint32_t)((2 * h) * PQBUFW * 4) + (uint32_t)((tid & 31) * 8);
        const uint32_t pq1 = pq0 + (uint32_t)(PQBUFW * 4);
        const ulonglong2* __restrict__ wAp = g_wpA + tid64;
        const ulonglong2* __restrict__ wBp = g_wpB + tid64;

        #pragma unroll 8
        for (int u = 0; u < 32; u++) {
            ulonglong2 wa = __ldg(&wAp[u * 64]);
            ulonglong2 wb = __ldg(&wBp[u * 64]);
            unsigned long long v0, v1;                 // {col even, col odd} of each pair
            const uint32_t uoff = (uint32_t)(u * (PQU * 4));
            asm volatile("ld.shared.b64 %0, [%1];" : "=l"(v0) : "r"(pq0 + uoff));
            asm volatile("ld.shared.b64 %0, [%1];" : "=l"(v1) : "r"(pq1 + uoff));
            FMA2(z2[0][0], wa.x, v0); FMA2(z2[0][1], wa.x, v1);
            FMA2(z2[1][0], wa.y, v0); FMA2(z2[1][1], wa.y, v1);
            FMA2(z2[2][0], wb.x, v0); FMA2(z2[2][1], wb.x, v1);
            FMA2(z2[3][0], wb.y, v0); FMA2(z2[3][1], wb.y, v1);
        }

        // ---- Dt overlay into dead smT cols (8G+4h .. +3) ----
        const int ca = 8 * G + 4 * h;
        #pragma unroll
        for (int m = 0; m < 4; m++) {
            int t = tid64 + 64 * m;
            sm[(ca)     * TSTR + t] = __uint_as_float((uint32_t)z2[m][0]);
            sm[(ca + 1) * TSTR + t] = __uint_as_float((uint32_t)(z2[m][0] >> 32));
            sm[(ca + 2) * TSTR + t] = __uint_as_float((uint32_t)z2[m][1]);
            sm[(ca + 3) * TSTR + t] = __uint_as_float((uint32_t)(z2[m][1] >> 32));
        }
        __syncthreads();                               // PQ reuse + Dt visibility
    }

    // ---- Windowed overlap-add epilogue: 4 consecutive k/thread, 7 segs/thread ----
    {
        const int lt = tid & 63;
        const int h  = tid >> 6;                       // segment half
        const int k0 = 4 * lt;                         // 0..252
        const bool lo = (lt < 32);                     // warp-uniform
        float wA[4], wB[4];
        #pragma unroll
        for (int d = 0; d < 4; d++) {
            int k = k0 + d;
            wA[d] = __ldg(&g_win[k]) * (lo ? -1.0f : 1.0f);
            wB[d] = __ldg(&g_win[k + 256]);
        }
        const int aOff = lo ? (124 - k0) : (k0 - 128); // word offset of zA quad
        const int bOff = lo ? (k0 + 128) : (380 - k0); // word offset of zB quad
        float* ob = out + (size_t)b * LOUT + k0;

        #pragma unroll 2
        for (int ii = 0; ii < 7; ii++) {
            int i = 7 * h + ii;
            int s = s0 + i;
            if (s <= 4096) {
                float4 a4 = *reinterpret_cast<const float4*>(sm + (i + 1) * TSTR + aOff);
                float4 b4 = *reinterpret_cast<const float4*>(sm + i * TSTR + bOff);
                float av[4], bv[4];
                if (lo) { av[0]=a4.w; av[1]=a4.z; av[2]=a4.y; av[3]=a4.x;
                          bv[0]=b4.x; bv[1]=b4.y; bv[2]=b4.z; bv[3]=b4.w; }
                else    { av[0]=a4.x; av[1]=a4.y; av[2]=a4.z; av[3]=a4.w;
                          bv[0]=b4.w; bv[1]=b4.z; bv[2]=b4.y; bv[3]=b4.x; }
                float4 o;
                o.x = wA[0] * av[0] + wB[0] * bv[0];
                o.y = wA[1] * av[1] + wB[1] * bv[1];
                o.z = wA[2] * av[2] + wB[2] * bv[2];
                o.w = wA[3] * av[3] + wB[3] * bv[3];
                *reinterpret_cast<float4*>(ob + (size_t)s * 256) = o;
            }
        }
    }
}

extern "C" void kernel_launch(void* const* d_in, const int* in_sizes, int n_in,
                              void* d_out, int out_size)
{
    const float* spec    = (const float*)d_in[0];   // [16,1,256,4096]
    const float* kernels = (const float*)d_in[1];   // [512,256]
    float* out = (float*)d_out;                     // [16,1048832]

    prep_kernel<<<10, 256>>>(kernels);              // 2560 threads

    cudaFuncSetAttribute(imdct_main_kernel,
                         cudaFuncAttributeMaxDynamicSharedMemorySize, SMBYTES);
    dim3 grid((4097 + NSEG - 1) / NSEG, 16);        // (293, 16)
    imdct_main_kernel<<<grid, 128, SMBYTES>>>(spec, out);
}

// round 17
// speedup vs baseline: 1.0144x; 1.0144x over previous
#include <cuda_runtime.h>
#include <cstdint>
#include <math.h>

// IMDCT round 17: R15 base (108us), minus spec smem staging (direct GMEM S loads),
// plus stage-2 weight prefetch. Two-stage Cooley-Tukey, FFMA-imm stage-1, butterfly.
//
//   z_col[t] = sum_u W2[t][u]*PQ[u][tau], tau=t&31
//   PQ[f0][tau]    = sum_f1 S[16f1+f0]*cos(pi*f1*(2tau+1)/32)
//   PQ[16+f0][tau] = sum_f1 S[16f1+f0]*sin(pi*f1*(2tau+1)/32)
//   butterfly: row tau+16 = (-1)^f1 * row tau -> E/O sums, P = E+-O.
// W2 from input kernels. Epilogue: windowed overlap-add.
//
// Block 128 thr = 4 warps, NSEG=14, 16 cols = 2 groups of 8; 4 blocks/SM.
// smem: Dt[16][272] ++ PQ[8][1088] = 52,224 B.

#define NFREQ    256
#define TFRAMES  4096
#define NSEG     14
#define NCOLS    16
#define TSTR     272                       // Dt col stride (words); %32==16
#define SMTW     (NCOLS * TSTR)            // 4352 words
#define USTR     34                        // PQ u-stride (words)
#define PQCOLW   1088                      // PQ col stride (words)
#define SMWORDS  (SMTW + 8 * PQCOLW)       // 13056
#define SMBYTES  (SMWORDS * 4)             // 52,224 B
#define LOUT     1048832

#define FMA2(acc, a, v) \
    asm("fma.rn.f32x2 %0, %1, %2, %0;" : "+l"(acc) : "l"(a), "l"(v))
#define PACK2(dst, x) \
    asm("mov.b64 %0, {%1, %1};" : "=l"(dst) : "r"(__float_as_uint(x)))

// cos(k*pi/32), k = 0..63 — folded to FFMA immediates (indices compile-time).
static __device__ constexpr float CP64[64] = {
     1.00000000f,  0.99518473f,  0.98078528f,  0.95694034f,
     0.92387953f,  0.88192126f,  0.83146961f,  0.77301045f,
     0.70710678f,  0.63439328f,  0.55557023f,  0.47139674f,
     0.38268343f,  0.29028468f,  0.19509032f,  0.09801714f,
     0.00000000f, -0.09801714f, -0.19509032f, -0.29028468f,
    -0.38268343f, -0.47139674f, -0.55557023f, -0.63439328f,
    -0.70710678f, -0.77301045f, -0.83146961f, -0.88192126f,
    -0.92387953f, -0.95694034f, -0.98078528f, -0.99518473f,
    -1.00000000f, -0.99518473f, -0.98078528f, -0.95694034f,
    -0.92387953f, -0.88192126f, -0.83146961f, -0.77301045f,
    -0.70710678f, -0.63439328f, -0.55557023f, -0.47139674f,
    -0.38268343f, -0.29028468f, -0.19509032f, -0.09801714f,
     0.00000000f,  0.09801714f,  0.19509032f,  0.29028468f,
     0.38268343f,  0.47139674f,  0.55557023f,  0.63439328f,
     0.70710678f,  0.77301045f,  0.83146961f,  0.88192126f,
     0.92387953f,  0.95694034f,  0.98078528f,  0.99518473f
};

__device__ float4 g_w2[32 * 64];    // [u][tid64]: {W2[t], W2[t+64], W2[t+128], W2[t+192]}
__device__ float  g_win[512];

__global__ void prep_kernel(const float* __restrict__ kernels)
{
    int idx = blockIdx.x * blockDim.x + threadIdx.x;   // 2560 threads
    if (idx < 2048) {                                  // g_w2
        int u = idx >> 6, j = idx & 63;
        float r[4];
        #pragma unroll
        for (int m = 0; m < 4; m++) {
            int t = j + 64 * m;
            float wn = sinf((float)M_PI * (float)(2 * (128 + t) + 1) * (1.0f / 1024.0f));
            float sc = 1.0f / (128.0f * wn);
            if (u < 16)
                r[m] = kernels[(128 + t) * 256 + u] * sc;
            else {
                float sgn = (t & 1) ? 1.0f : -1.0f;    // -(-1)^t
                r[m] = sgn * kernels[(128 + t) * 256 + (255 - (u - 16))] * sc;
            }
        }
        g_w2[u * 64 + j] = make_float4(r[0], r[1], r[2], r[3]);
    } else if (idx < 2560) {
        int t = idx - 2048;
        g_win[t] = sinf((float)M_PI * (float)(2 * t + 1) * (1.0f / 1024.0f));
    }
}

__global__ __launch_bounds__(128, 4)
void imdct_main_kernel(const float* __restrict__ spec, float* __restrict__ out)
{
    extern __shared__ float sm[];                      // Dt[16][272] ++ PQ[8][1088]
    const int tid  = threadIdx.x;                      // 0..127
    const int lane = tid & 31;
    const int w    = tid >> 5;                         // warp 0..3
    const int cp   = lane >> 4;                        // stage-1 col select in warp
    const int f0   = lane & 15;                        // stage-1 u-base
    const int b    = blockIdx.y;
    const int s0   = blockIdx.x * NSEG;

    const float* specB = spec + (size_t)b * NFREQ * TFRAMES;
    const uint32_t smb = (uint32_t)__cvta_generic_to_shared(sm);
    const uint32_t pqb = smb + SMTW * 4;

    #pragma unroll 1
    for (int G = 0; G < 2; G++) {
        // ======== stage 1: lane -> col 8G+2w+cp; S direct from GMEM ========
        const int cl = 2 * w + cp;                     // group-local col 0..7
        const int cg = s0 - 1 + 8 * G + cl;            // global spec column
        const bool inb = (cg >= 0 && cg < TFRAMES);
        const float* sp = specB + (size_t)f0 * TFRAMES + (inb ? cg : 0);

        float S[16];                                   // S[f1] = spec[b][16f1+f0][cg]
        #pragma unroll
        for (int f1 = 0; f1 < 16; f1++) {
            float v = __ldg(sp + (size_t)f1 * (16 * TFRAMES));
            S[f1] = inb ? v : 0.0f;
        }

        const uint32_t pqP = pqb + (uint32_t)((cl * PQCOLW + f0 * USTR) * 4);
        const uint32_t pqQ = pqP + (uint32_t)(16 * USTR * 4);

        #pragma unroll
        for (int tp = 0; tp < 8; tp++) {               // taus 2tp, 2tp+1 (+16 via butterfly)
            float ep0 = 0.f, op0 = 0.f, eq0 = 0.f, oq0 = 0.f;
            float ep1 = 0.f, op1 = 0.f, eq1 = 0.f, oq1 = 0.f;
            #pragma unroll
            for (int f1 = 0; f1 < 16; f1++) {
                const int k0 = (f1 * (4 * tp + 1)) & 63;
                const int k1 = (f1 * (4 * tp + 3)) & 63;
                const float c0 = CP64[k0], s0c = CP64[(k0 + 48) & 63];
                const float c1 = CP64[k1], s1c = CP64[(k1 + 48) & 63];
                if (f1 & 1) {
                    op0 = fmaf(S[f1], c0, op0);  oq0 = fmaf(S[f1], s0c, oq0);
                    op1 = fmaf(S[f1], c1, op1);  oq1 = fmaf(S[f1], s1c, oq1);
                } else {
                    ep0 = fmaf(S[f1], c0, ep0);  eq0 = fmaf(S[f1], s0c, eq0);
                    ep1 = fmaf(S[f1], c1, ep1);  eq1 = fmaf(S[f1], s1c, eq1);
                }
            }
            // butterfly -> P/Q rows tau and tau+16, stored as b64 pairs
            unsigned long long Plo, Phi, Qlo, Qhi;
            asm("mov.b64 %0, {%1, %2};" : "=l"(Plo)
                : "r"(__float_as_uint(ep0 + op0)), "r"(__float_as_uint(ep1 + op1)));
            asm("mov.b64 %0, {%1, %2};" : "=l"(Phi)
                : "r"(__float_as_uint(ep0 - op0)), "r"(__float_as_uint(ep1 - op1)));
            asm("mov.b64 %0, {%1, %2};" : "=l"(Qlo)
                : "r"(__float_as_uint(eq0 + oq0)), "r"(__float_as_uint(eq1 + oq1)));
            asm("mov.b64 %0, {%1, %2};" : "=l"(Qhi)
                : "r"(__float_as_uint(eq0 - oq0)), "r"(__float_as_uint(eq1 - oq1)));
            asm volatile("st.shared.b64 [%0], %1;" :: "r"(pqP + 8 * tp),      "l"(Plo));
            asm volatile("st.shared.b64 [%0], %1;" :: "r"(pqP + 8 * tp + 64), "l"(Phi));
            asm volatile("st.shared.b64 [%0], %1;" :: "r"(pqQ + 8 * tp),      "l"(Qlo));
            asm volatile("st.shared.b64 [%0], %1;" :: "r"(pqQ + 8 * tp + 64), "l"(Qhi));
        }
        __syncthreads();

        // ======== stage 2: half-block per 4 cols; t = tid64 + 64m; prefetched weights ========
        const int tid64 = tid & 63;
        const int cl0   = (tid >> 6) * 4;              // 0 or 4
        unsigned long long z2[4][2];
        #pragma unroll
        for (int m = 0; m < 4; m++) { z2[m][0] = 0; z2[m][1] = 0; }
        const uint32_t pql = pqb + (uint32_t)((cl0 * PQCOLW + (tid & 31)) * 4);
        const float4* __restrict__ w2p = ((const float4*)g_w2) + tid64;

        float4 wnext = __ldg(&w2p[0]);
        #pragma unroll 8
        for (int u = 0; u < 32; u++) {
            float4 w4 = wnext;
            wnext = __ldg(&w2p[(u < 31 ? u + 1 : 31) * 64]);
            uint32_t uoff = (uint32_t)(u * USTR * 4);
            uint32_t p0, p1, p2, p3;
            asm volatile("ld.shared.b32 %0, [%1];" : "=r"(p0) : "r"(pql + uoff));
            asm volatile("ld.shared.b32 %0, [%1];" : "=r"(p1) : "r"(pql + uoff + PQCOLW * 4));
            asm volatile("ld.shared.b32 %0, [%1];" : "=r"(p2) : "r"(pql + uoff + 2 * PQCOLW * 4));
            asm volatile("ld.shared.b32 %0, [%1];" : "=r"(p3) : "r"(pql + uoff + 3 * PQCOLW * 4));
            unsigned long long v01, v23;
            asm("mov.b64 %0, {%1, %2};" : "=l"(v01) : "r"(p0), "r"(p1));
            asm("mov.b64 %0, {%1, %2};" : "=l"(v23) : "r"(p2), "r"(p3));
            unsigned long long m0, m1, m2, m3;
            PACK2(m0, w4.x); PACK2(m1, w4.y); PACK2(m2, w4.z); PACK2(m3, w4.w);
            FMA2(z2[0][0], m0, v01); FMA2(z2[0][1], m0, v23);
            FMA2(z2[1][0], m1, v01); FMA2(z2[1][1], m1, v23);
            FMA2(z2[2][0], m2, v01); FMA2(z2[2][1], m2, v23);
            FMA2(z2[3][0], m3, v01); FMA2(z2[3][1], m3, v23);
        }

        // ---- Dt overlay: cols (8G+cl0 .. +3) ----
        const int ca = 8 * G + cl0;
        #pragma unroll
        for (int m = 0; m < 4; m++) {
            int t = tid64 + 64 * m;
            sm[(ca)     * TSTR + t] = __uint_as_float((uint32_t)z2[m][0]);
            sm[(ca + 1) * TSTR + t] = __uint_as_float((uint32_t)(z2[m][0] >> 32));
            sm[(ca + 2) * TSTR + t] = __uint_as_float((uint32_t)z2[m][1]);
            sm[(ca + 3) * TSTR + t] = __uint_as_float((uint32_t)(z2[m][1] >> 32));
        }
        __syncthreads();                               // PQ reuse + Dt visibility
    }

    // ---- Windowed overlap-add epilogue: 4 consecutive k/thread, 7 segs/thread ----
    {
        const int lt = tid & 63;
        const int h  = tid >> 6;                       // segment half
        const int k0 = 4 * lt;                         // 0..252
        const bool lo = (lt < 32);                     // warp-uniform
        float wA[4], wB[4];
        #pragma unroll
        for (int d = 0; d < 4; d++) {
            int k = k0 + d;
            wA[d] = __ldg(&g_win[k]) * (lo ? -1.0f : 1.0f);
            wB[d] = __ldg(&g_win[k + 256]);
        }
        const int aOff = lo ? (124 - k0) : (k0 - 128); // word offset of zA quad
        const int bOff = lo ? (k0 + 128) : (380 - k0); // word offset of zB quad
        float* ob = out + (size_t)b * LOUT + k0;

        #pragma unroll 2
        for (int ii = 0; ii < 7; ii++) {
            int i = 7 * h + ii;
            int s = s0 + i;
            if (s <= 4096) {
                float4 a4 = *reinterpret_cast<const float4*>(sm + (i + 1) * TSTR + aOff);
                float4 b4 = *reinterpret_cast<const float4*>(sm + i * TSTR + bOff);
                float av[4], bv[4];
                if (lo) { av[0]=a4.w; av[1]=a4.z; av[2]=a4.y; av[3]=a4.x;
                          bv[0]=b4.x; bv[1]=b4.y; bv[2]=b4.z; bv[3]=b4.w; }
                else    { av[0]=a4.x; av[1]=a4.y; av[2]=a4.z; av[3]=a4.w;
                          bv[0]=b4.w; bv[1]=b4.z; bv[2]=b4.y; bv[3]=b4.x; }
                float4 o;
                o.x = wA[0] * av[0] + wB[0] * bv[0];
                o.y = wA[1] * av[1] + wB[1] * bv[1];
                o.z = wA[2] * av[2] + wB[2] * bv[2];
                o.w = wA[3] * av[3] + wB[3] * bv[3];
                *reinterpret_cast<float4*>(ob + (size_t)s * 256) = o;
            }
        }
    }
}

extern "C" void kernel_launch(void* const* d_in, const int* in_sizes, int n_in,
                              void* d_out, int out_size)
{
    const float* spec    = (const float*)d_in[0];   // [16,1,256,4096]
    const float* kernels = (const float*)d_in[1];   // [512,256]
    float* out = (float*)d_out;                     // [16,1048832]

    prep_kernel<<<10, 256>>>(kernels);              // 2560 threads

    cudaFuncSetAttribute(imdct_main_kernel,
                         cudaFuncAttributeMaxDynamicSharedMemorySize, SMBYTES);
    dim3 grid((4097 + NSEG - 1) / NSEG, 16);        // (293, 16)
    imdct_main_kernel<<<grid, 128, SMBYTES>>>(spec, out);
}